// round 2
// baseline (speedup 1.0000x reference)
#include <cuda_runtime.h>
#include <cstdint>

#define NB 32
#define H1 224
#define P1 (H1*H1)      // 50176
#define H2 112
#define P2 (H2*H2)      // 12544
#define H3 56
#define P3 (H3*H3)      // 3136

// padded layouts (pads are never written -> stay zero from static init)
#define BXS 228                    // binx col stride
#define BXR 226                    // binx rows (ih+1 in [0,225])
#define H1S 228                    // h1 col stride
#define H1R 225                    // h1 rows (ih+1 in [0,224])
#define H2S 116                    // h2 col stride
#define H2R 113                    // h2 rows (ih+1 in [0,112])

// ---------------- scratch ----------------
__device__ uint32_t            g_binx[NB*BXR*BXS];
__device__ uint32_t            g_h1[NB*H1R*H1S];
__device__ unsigned long long  g_h2[NB*H2R*H2S];
__device__ int                 g_cnt[NB*128];
__device__ uint32_t            g_w1[32];
__device__ uint32_t            g_w2[64*9];
__device__ unsigned long long  g_w3[128*9];
__device__ int g_S1[9*32];       // border-type thresholds
__device__ int g_S2[4*64];
__device__ int g_S3[4*128];
__device__ int g_F1[32], g_F2[64], g_F3[128];
__device__ uint32_t g_Finit1, g_Finit2lo, g_Finit2hi;

// -------- integer threshold for sign(BN(a)) with exact fp32 semantics --------
__device__ __forceinline__ void calc_thresh(float g, float bb, float m, float v,
                                            int K, int* T, int* F)
{
    float inv = __fdiv_rn(g, sqrtf(__fadd_rn(v, 1e-5f)));
    float c0  = __fsub_rn(bb, __fmul_rn(m, inv));
    if (inv > 0.f) {
        int A0 = K + 1;
        for (int a = -K; a <= K; a++) {
            float f = __fadd_rn(__fmul_rn((float)a, inv), c0);
            if (f >= 0.f) { A0 = a; break; }
        }
        *T = A0; *F = 0;
    } else if (inv < 0.f) {
        int A1 = -K - 1;
        for (int a = K; a >= -K; a--) {
            float f = __fadd_rn(__fmul_rn((float)a, inv), c0);
            if (f >= 0.f) { A1 = a; break; }
        }
        *T = A1 + 1; *F = 1;
    } else {
        if (c0 < 0.f) { *T =  K + 1;  *F = 0; }
        else          { *T = -(K+1);  *F = 0; }
    }
}

// ---------------- precompute ----------------
__global__ void precompute_kernel(
    const float* w1, const float* w2, const float* w3,
    const float* g1, const float* b1, const float* m1, const float* v1,
    const float* g2, const float* b2, const float* m2, const float* v2,
    const float* g3, const float* b3, const float* m3, const float* v3)
{
    int t = threadIdx.x;
    if (t < 32) {
        uint32_t bits = 0;
        for (int ic = 0; ic < 3; ic++)
            for (int kh = 0; kh < 3; kh++)
                for (int kw = 0; kw < 3; kw++)
                    if (w1[((t*3 + ic)*3 + kh)*3 + kw] < 0.f)
                        bits |= 1u << ((kh*3 + kw)*3 + ic);
        g_w1[t] = bits;
        int T, F; calc_thresh(g1[t], b1[t], m1[t], v1[t], 27, &T, &F);
        g_F1[t] = F;
        for (int bt = 0; bt < 9; bt++) {
            int vt = bt / 3, hz = bt % 3;
            int inv = 0;
            if (vt == 1) inv |= (1|2|4);          // taps 0,1,2  (top)
            if (vt == 2) inv |= (64|128|256);     // taps 6,7,8  (bottom)
            if (hz == 1) inv |= (1|8|64);         // taps 0,3,6  (left)
            if (hz == 2) inv |= (4|32|256);       // taps 2,5,8  (right)
            int nv = 27 - 3*__popc(inv);
            int corr = 0;
            for (int tap = 0; tap < 9; tap++)
                if ((inv >> tap) & 1) corr += __popc((bits >> (tap*3)) & 7u);
            g_S1[bt*32 + t] = ((nv - T) >> 1) + corr + 1;
        }
    }
    if (t < 64) {
        uint32_t wt[9];
        for (int tap = 0; tap < 9; tap++) {
            int kh = tap / 3, kw = tap % 3;
            uint32_t bits = 0;
            for (int ic = 0; ic < 32; ic++)
                if (w2[((t*32 + ic)*3 + kh)*3 + kw] < 0.f) bits |= 1u << ic;
            g_w2[t*9 + tap] = bits; wt[tap] = bits;
        }
        int T, F; calc_thresh(g2[t], b2[t], m2[t], v2[t], 288, &T, &F);
        g_F2[t] = F;
        for (int bt = 0; bt < 4; bt++) {
            int inv = 0;
            if (bt & 1) inv |= (1|2|4);           // top
            if (bt & 2) inv |= (1|8|64);          // left
            int nv = 32 * (9 - __popc(inv));
            int corr = 0;
            for (int tap = 0; tap < 9; tap++)
                if ((inv >> tap) & 1) corr += __popc(wt[tap]);
            g_S2[bt*64 + t] = ((nv - T) >> 1) + corr + 1;
        }
    }
    if (t < 128) {
        unsigned long long wt[9];
        for (int tap = 0; tap < 9; tap++) {
            int kh = tap / 3, kw = tap % 3;
            unsigned long long bits = 0;
            for (int ic = 0; ic < 64; ic++)
                if (w3[((t*64 + ic)*3 + kh)*3 + kw] < 0.f) bits |= 1ull << ic;
            g_w3[t*9 + tap] = bits; wt[tap] = bits;
        }
        int T, F; calc_thresh(g3[t], b3[t], m3[t], v3[t], 576, &T, &F);
        g_F3[t] = F;
        for (int bt = 0; bt < 4; bt++) {
            int inv = 0;
            if (bt & 1) inv |= (1|2|4);
            if (bt & 2) inv |= (1|8|64);
            int nv = 64 * (9 - __popc(inv));
            int corr = 0;
            for (int tap = 0; tap < 9; tap++)
                if ((inv >> tap) & 1) corr += __popcll(wt[tap]);
            g_S3[bt*128 + t] = ((nv - T) >> 1) + corr + 1;
        }
    }
    __syncthreads();
    if (t == 0) {
        uint32_t f = 0;
        for (int oc = 0; oc < 32; oc++) f |= ((uint32_t)g_F1[oc]) << oc;
        g_Finit1 = f;
        uint32_t lo = 0, hi = 0;
        for (int oc = 0; oc < 32; oc++) lo |= ((uint32_t)g_F2[oc]) << oc;
        for (int oc = 0; oc < 32; oc++) hi |= ((uint32_t)g_F2[oc+32]) << oc;
        g_Finit2lo = lo; g_Finit2hi = hi;
    }
    for (int j = t; j < NB*128; j += blockDim.x) g_cnt[j] = 0;
}

// ---------------- binarize input into padded layout ----------------
__global__ void binx_kernel(const float* __restrict__ x)
{
    int i = blockIdx.x * blockDim.x + threadIdx.x;   // exact NB*P1
    int b = i / P1, p = i % P1;
    int oh = p / H1, ow = p % H1;
    const float* xb = x + (size_t)b * 3 * P1 + p;
    uint32_t bits = (xb[0]      < 0.f ? 1u : 0u)
                  | (xb[P1]     < 0.f ? 2u : 0u)
                  | (xb[2*P1]   < 0.f ? 4u : 0u);
    g_binx[b*(BXR*BXS) + (oh+1)*BXS + (ow+1)] = bits;
}

// ---------------- layer 1: 3ch -> 32ch, stride 1, 4 px/thread ----------------
__global__ void layer1_kernel()
{
    __shared__ uint32_t sw[32];
    __shared__ int sS[9*32];
    if (threadIdx.x < 32) sw[threadIdx.x] = g_w1[threadIdx.x];
    for (int j = threadIdx.x; j < 9*32; j += blockDim.x) sS[j] = g_S1[j];
    __syncthreads();

    int i = blockIdx.x * blockDim.x + threadIdx.x;   // NB*224*56 = 401408 exact
    int b = i / 12544, rem = i % 12544;
    int oh = rem / 56, g = rem % 56;
    int ow0 = g * 4;

    const uint32_t* bx = g_binx + b*(BXR*BXS) + oh*BXS + ow0;
    uint32_t c[3][6];
    #pragma unroll
    for (int kh = 0; kh < 3; kh++)
        #pragma unroll
        for (int m = 0; m < 6; m++) c[kh][m] = bx[kh*BXS + m];

    uint32_t xv0 = 0, xv1 = 0, xv2 = 0, xv3 = 0;
    #pragma unroll
    for (int kh = 0; kh < 3; kh++)
        #pragma unroll
        for (int kw = 0; kw < 3; kw++) {
            int sh = (kh*3 + kw)*3;
            xv0 |= c[kh][kw]   << sh;
            xv1 |= c[kh][kw+1] << sh;
            xv2 |= c[kh][kw+2] << sh;
            xv3 |= c[kh][kw+3] << sh;
        }

    int vt = (oh == 0) ? 1 : ((oh == 223) ? 2 : 0);
    const int* Sm = &sS[(vt*3) * 32];
    const int* Sa = &sS[(vt*3 + ((g == 0)  ? 1 : 0)) * 32];   // pixel 0
    const int* Sb = &sS[(vt*3 + ((g == 55) ? 2 : 0)) * 32];   // pixel 3

    uint32_t fi = g_Finit1;
    uint32_t o0 = fi, o1 = fi, o2 = fi, o3 = fi;
    #pragma unroll
    for (int oc = 0; oc < 32; oc++) {
        uint32_t w = sw[oc];
        uint32_t mb = 1u << oc;
        int srest = Sm[oc];
        if (__popc(xv0 ^ w) >= Sa[oc]) o0 ^= mb;
        if (__popc(xv1 ^ w) >= srest)  o1 ^= mb;
        if (__popc(xv2 ^ w) >= srest)  o2 ^= mb;
        if (__popc(xv3 ^ w) >= Sb[oc]) o3 ^= mb;
    }
    uint32_t* o = g_h1 + b*(H1R*H1S) + (oh+1)*H1S + (ow0+1);
    o[0] = o0; o[1] = o1; o[2] = o2; o[3] = o3;
}

// ---------------- layer 2: 32ch -> 64ch, stride 2, 4 px/thread ----------------
#define L2PIX(CJ, SS, ACC) { \
    int s = __popc(c[0][CJ]^w0)+__popc(c[0][CJ+1]^w1)+__popc(c[0][CJ+2]^w2) \
          + __popc(c[1][CJ]^w3)+__popc(c[1][CJ+1]^w4)+__popc(c[1][CJ+2]^w5) \
          + __popc(c[2][CJ]^w6)+__popc(c[2][CJ+1]^w7)+__popc(c[2][CJ+2]^w8); \
    if (s >= (SS)) (ACC) ^= mb; }

__global__ void layer2_kernel()
{
    __shared__ uint32_t sw[64*9];
    __shared__ int sS[4*64];
    for (int j = threadIdx.x; j < 64*9; j += blockDim.x) sw[j] = g_w2[j];
    for (int j = threadIdx.x; j < 4*64; j += blockDim.x) sS[j] = g_S2[j];
    __syncthreads();

    int i = blockIdx.x * blockDim.x + threadIdx.x;   // NB*112*28 = 100352 exact
    int b = i / 3136, rem = i % 3136;
    int oh = rem / 28, g = rem % 28;

    const uint32_t* h1 = g_h1 + b*(H1R*H1S) + (2*oh)*H1S + 8*g;
    uint32_t c[3][9];
    #pragma unroll
    for (int kh = 0; kh < 3; kh++)
        #pragma unroll
        for (int m = 0; m < 9; m++) c[kh][m] = h1[kh*H1S + m];

    int vt = (oh == 0) ? 1 : 0;
    const int* Sm = &sS[vt * 64];
    const int* Sp = &sS[(vt + ((g == 0) ? 2 : 0)) * 64];

    uint32_t l0 = g_Finit2lo, l1 = l0, l2 = l0, l3 = l0;
    uint32_t h0 = g_Finit2hi, h1r = h0, h2r = h0, h3r = h0;

    #pragma unroll 4
    for (int oc = 0; oc < 32; oc++) {
        const uint32_t* w = &sw[oc*9];
        uint32_t w0=w[0],w1=w[1],w2=w[2],w3=w[3],w4=w[4],w5=w[5],w6=w[6],w7=w[7],w8=w[8];
        uint32_t mb = 1u << oc;
        int srest = Sm[oc];
        L2PIX(0, Sp[oc], l0) L2PIX(2, srest, l1) L2PIX(4, srest, l2) L2PIX(6, srest, l3)
    }
    #pragma unroll 4
    for (int oc = 32; oc < 64; oc++) {
        const uint32_t* w = &sw[oc*9];
        uint32_t w0=w[0],w1=w[1],w2=w[2],w3=w[3],w4=w[4],w5=w[5],w6=w[6],w7=w[7],w8=w[8];
        uint32_t mb = 1u << (oc - 32);
        int srest = Sm[oc];
        L2PIX(0, Sp[oc], h0) L2PIX(2, srest, h1r) L2PIX(4, srest, h2r) L2PIX(6, srest, h3r)
    }
    unsigned long long* o = g_h2 + b*(H2R*H2S) + (oh+1)*H2S + (4*g+1);
    o[0] = ((unsigned long long)h0  << 32) | l0;
    o[1] = ((unsigned long long)h1r << 32) | l1;
    o[2] = ((unsigned long long)h2r << 32) | l2;
    o[3] = ((unsigned long long)h3r << 32) | l3;
}

// ---------------- layer 3: 64ch -> 128ch, stride 2, 2 px/thread + count ------
#define L3PIX(CJ) ( \
    __popcll(c[0][CJ]^w0)+__popcll(c[0][CJ+1]^w1)+__popcll(c[0][CJ+2]^w2) \
  + __popcll(c[1][CJ]^w3)+__popcll(c[1][CJ+1]^w4)+__popcll(c[1][CJ+2]^w5) \
  + __popcll(c[2][CJ]^w6)+__popcll(c[2][CJ+1]^w7)+__popcll(c[2][CJ+2]^w8) )

__global__ void layer3_kernel()
{
    __shared__ unsigned long long sw[128*9];
    __shared__ int sS[4*128];
    __shared__ int sF[128];
    __shared__ int scnt[128];
    for (int j = threadIdx.x; j < 128*9; j += blockDim.x) sw[j] = g_w3[j];
    for (int j = threadIdx.x; j < 4*128; j += blockDim.x) sS[j] = g_S3[j];
    if (threadIdx.x < 128) { sF[threadIdx.x] = g_F3[threadIdx.x]; scnt[threadIdx.x] = 0; }
    __syncthreads();

    int b = blockIdx.y;
    int rem = blockIdx.x * blockDim.x + threadIdx.x;  // 7 blocks x 224 = 1568 exact
    int oh = rem / 28, g = rem % 28;

    const unsigned long long* h2 = g_h2 + b*(H2R*H2S) + (2*oh)*H2S + 4*g;
    unsigned long long c[3][5];
    #pragma unroll
    for (int kh = 0; kh < 3; kh++)
        #pragma unroll
        for (int m = 0; m < 5; m++) c[kh][m] = h2[kh*H2S + m];

    int vt = (oh == 0) ? 1 : 0;
    const int* Sm = &sS[vt * 128];
    const int* Sp = &sS[(vt + ((g == 0) ? 2 : 0)) * 128];
    int lane = threadIdx.x & 31;

    #pragma unroll 2
    for (int oc = 0; oc < 128; oc++) {
        const unsigned long long* w = &sw[oc*9];
        unsigned long long w0=w[0],w1=w[1],w2=w[2],w3=w[3],w4=w[4],w5=w[5],w6=w[6],w7=w[7],w8=w[8];
        int s0 = L3PIX(0);
        int s1 = L3PIX(2);
        unsigned bal0 = __ballot_sync(0xFFFFFFFFu, s0 >= Sp[oc]);
        unsigned bal1 = __ballot_sync(0xFFFFFFFFu, s1 >= Sm[oc]);
        if (lane == 0) {
            int cnt = __popc(bal0) + __popc(bal1);
            if (sF[oc]) cnt = 64 - cnt;
            atomicAdd(&scnt[oc], cnt);
        }
    }
    __syncthreads();
    if (threadIdx.x < 128)
        atomicAdd(&g_cnt[b*128 + threadIdx.x], scnt[threadIdx.x]);
}

// ---------------- fc ----------------
__global__ void fc_kernel(const float* __restrict__ fcw,
                          const float* __restrict__ fcb,
                          float* __restrict__ out)
{
    int t = threadIdx.x;
    if (t >= NB*2) return;
    int b = t >> 1, k = t & 1;
    float s = fcb[k];
    const float* wr = fcw + k*128;
    for (int c = 0; c < 128; c++) {
        float mean = (float)(P3 - 2*g_cnt[b*128 + c]) / (float)P3;
        s += mean * wr[c];
    }
    out[b*2 + k] = s;
}

// ---------------- launch ----------------
extern "C" void kernel_launch(void* const* d_in, const int* in_sizes, int n_in,
                              void* d_out, int out_size)
{
    const float* x   = (const float*)d_in[0];
    const float* w1  = (const float*)d_in[1];
    const float* w2  = (const float*)d_in[2];
    const float* w3  = (const float*)d_in[3];
    const float* g1  = (const float*)d_in[4];
    const float* b1  = (const float*)d_in[5];
    const float* m1  = (const float*)d_in[6];
    const float* v1  = (const float*)d_in[7];
    const float* g2  = (const float*)d_in[8];
    const float* b2  = (const float*)d_in[9];
    const float* m2  = (const float*)d_in[10];
    const float* v2  = (const float*)d_in[11];
    const float* g3  = (const float*)d_in[12];
    const float* b3  = (const float*)d_in[13];
    const float* m3  = (const float*)d_in[14];
    const float* v3  = (const float*)d_in[15];
    const float* fcw = (const float*)d_in[16];
    const float* fcb = (const float*)d_in[17];
    float* out = (float*)d_out;

    precompute_kernel<<<1, 256>>>(w1, w2, w3,
                                  g1, b1, m1, v1,
                                  g2, b2, m2, v2,
                                  g3, b3, m3, v3);

    binx_kernel<<<(NB*P1)/256, 256>>>(x);          // 6272 blocks, exact
    layer1_kernel<<<(NB*224*56)/256, 256>>>();     // 1568 blocks, exact
    layer2_kernel<<<(NB*112*28)/256, 256>>>();     // 392 blocks, exact
    dim3 grid3(7, NB);                             // 7*224 = 1568 groups/image
    layer3_kernel<<<grid3, 224>>>();
    fc_kernel<<<1, 64>>>(fcw, fcb, out);
}